// round 1
// baseline (speedup 1.0000x reference)
#include <cuda_runtime.h>
#include <math.h>

#define NB 4
#define NPER 4096
#define EPER 49152
#define NN (NB*NPER)        // 16384 nodes
#define ETOT (NB*EPER)      // 196608 edges
#define F 128
#define KF 20
#define NL 3
#define CUTF 5.0f
#define PIF 3.14159265358979323846f

// ---------------- scratch (device globals; zero-initialized) ----------------
__device__ float g_s  [NN*F];
__device__ float g_v  [NN*3*F];
__device__ float g_ds [NN*F];      // must be zero at start of each edge phase
__device__ float g_dv [NN*3*F];
__device__ float g_so [NN*3*F];
__device__ float g_hid[NN*F];
__device__ float g_min[NN*2*F];
__device__ float g_m  [NN*3*F];
__device__ float g_Uv [NN*3*F];
__device__ float g_Vv [NN*3*F];
__device__ float g_dot[NN*F];
__device__ float g_es [ETOT*KF];
__device__ float g_cut[ETOT];
__device__ float g_dir[ETOT*3];
__device__ int   g_send[ETOT];
__device__ int   g_recv[ETOT];
__device__ int   g_nact;
__device__ float g_zb[3*F];        // zero bias

// ---------------- generic tiled GEMM: C = act(A[M,K] @ W[N,K]^T + b) --------
template<int ACT>
__global__ __launch_bounds__(256)
void gemm_bias(const float* __restrict__ A, const float* __restrict__ W,
               const float* __restrict__ bias, float* __restrict__ C,
               int M, int Nout, int Kin) {
    __shared__ float As[64][17];
    __shared__ float Ws[64][17];
    int tid = threadIdx.x;
    int tx = tid & 15, ty = tid >> 4;
    int m0 = blockIdx.y * 64, n0 = blockIdx.x * 64;
    float acc[4][4] = {};
    for (int k0 = 0; k0 < Kin; k0 += 16) {
#pragma unroll
        for (int t = 0; t < 4; t++) {
            int e = tid + t * 256;
            int i = e >> 4, k = e & 15;
            As[i][k] = A[(size_t)(m0 + i) * Kin + k0 + k];
            Ws[i][k] = W[(size_t)(n0 + i) * Kin + k0 + k];
        }
        __syncthreads();
#pragma unroll
        for (int k = 0; k < 16; k++) {
            float a[4], b[4];
#pragma unroll
            for (int i = 0; i < 4; i++) a[i] = As[ty*4+i][k];
#pragma unroll
            for (int j = 0; j < 4; j++) b[j] = Ws[tx*4+j][k];
#pragma unroll
            for (int i = 0; i < 4; i++)
#pragma unroll
                for (int j = 0; j < 4; j++)
                    acc[i][j] += a[i] * b[j];
        }
        __syncthreads();
    }
#pragma unroll
    for (int i = 0; i < 4; i++) {
        int m = m0 + ty*4 + i;
#pragma unroll
        for (int j = 0; j < 4; j++) {
            int n = n0 + tx*4 + j;
            float val = acc[i][j] + bias[n];
            if (ACT) val = val / (1.0f + expf(-val));   // silu
            C[(size_t)m * Nout + n] = val;
        }
    }
}

// ---------------- misc kernels ----------------------------------------------
__global__ void reset_k() { g_nact = 0; }

// geometry + active-edge compaction (cut==0 edges contribute exactly 0)
__global__ void geom_k(const float* __restrict__ xyz, const float* __restrict__ cell,
                       const int* __restrict__ aedges, const float* __restrict__ edisp) {
    int e = blockIdx.x * blockDim.x + threadIdx.x;
    if (e >= ETOT) return;
    int b = e / EPER;
    int snd = aedges[2*e]   + b * NPER;
    int rcv = aedges[2*e+1] + b * NPER;
    const float* cb = cell + b * 9;
    float c0 = edisp[3*e], c1 = edisp[3*e+1], c2 = edisp[3*e+2];
    float dx[3];
#pragma unroll
    for (int d = 0; d < 3; d++) {
        float disp = c0 * cb[d] + c1 * cb[3+d] + c2 * cb[6+d];
        dx[d] = xyz[3*rcv+d] - (xyz[3*snd+d] + disp);
    }
    float dist = sqrtf(dx[0]*dx[0] + dx[1]*dx[1] + dx[2]*dx[2]);
    if (dist < CUTF) {
        int p = atomicAdd(&g_nact, 1);
        g_send[p] = snd; g_recv[p] = rcv;
        float inv  = 1.0f / dist;
        float invm = 1.0f / fmaxf(dist, 1e-12f);
#pragma unroll
        for (int k = 0; k < KF; k++)
            g_es[p*KF+k] = sinf(dist * (float)(k+1) * (PIF/CUTF)) * inv;
        g_cut[p] = 0.5f * (cosf(PIF * dist / CUTF) + 1.0f);
        g_dir[3*p]   = dx[0]*invm;
        g_dir[3*p+1] = dx[1]*invm;
        g_dir[3*p+2] = dx[2]*invm;
    }
}

// h = [atom_emb[node], V*potW + potb]  -> g_min (N x 256)
__global__ void init_h_k(const int* __restrict__ nodes, const float* __restrict__ Vflat,
                         const float* __restrict__ emb, const float* __restrict__ potW,
                         const float* __restrict__ potb) {
    int idx = blockIdx.x * blockDim.x + threadIdx.x;
    if (idx >= NN*F) return;
    int n = idx >> 7, j = idx & 127;
    g_min[n*256 + j]       = emb[nodes[n]*F + j];
    g_min[n*256 + 128 + j] = Vflat[n] * potW[j] + potb[j];
}

// v = E_flat[:, :, None] * vec_w
__global__ void init_v_k(const float* __restrict__ Eflat, const float* __restrict__ vecw) {
    int idx = blockIdx.x * blockDim.x + threadIdx.x;
    if (idx >= NN*3*F) return;
    int r = idx >> 7, j = idx & 127;
    g_v[idx] = Eflat[r] * vecw[j];
}

// per-edge message + scatter (only active/compacted edges)
#define EPB 32
__global__ __launch_bounds__(128)
void edge_k(const float* __restrict__ fW, const float* __restrict__ fb) {
    int nact = g_nact;
    int e0 = blockIdx.x * EPB;
    if (e0 >= nact) return;
    __shared__ float sW[384*21];
    __shared__ float sb[384];
    for (int i = threadIdx.x; i < 384*KF; i += 128)
        sW[(i/KF)*21 + (i%KF)] = fW[i];
    for (int i = threadIdx.x; i < 384; i += 128) sb[i] = fb[i];
    __syncthreads();
    int j = threadIdx.x;
    int e1 = min(e0 + EPB, nact);
    for (int e = e0; e < e1; e++) {
        int snd = g_send[e], rcv = g_recv[e];
        float cutv = g_cut[e];
        float esr[KF];
#pragma unroll
        for (int k = 0; k < KF; k++) esr[k] = g_es[e*KF+k];
        float fw0 = sb[j], fw1 = sb[j+128], fw2 = sb[j+256];
#pragma unroll
        for (int k = 0; k < KF; k++) {
            fw0 += sW[j*21+k]       * esr[k];
            fw1 += sW[(j+128)*21+k] * esr[k];
            fw2 += sW[(j+256)*21+k] * esr[k];
        }
        const float* sop = g_so + (size_t)snd * 384;
        float gsv = fw0 * cutv * sop[j];
        float gev = fw1 * cutv * sop[j+128];
        float gns = fw2 * cutv * sop[j+256];
        atomicAdd(&g_ds[rcv*F + j], g_s[snd*F + j] * gns);
        float d0 = g_dir[3*e], d1 = g_dir[3*e+1], d2 = g_dir[3*e+2];
        atomicAdd(&g_dv[(rcv*3+0)*F + j], g_v[(snd*3+0)*F + j]*gsv + gev*d0);
        atomicAdd(&g_dv[(rcv*3+1)*F + j], g_v[(snd*3+1)*F + j]*gsv + gev*d1);
        atomicAdd(&g_dv[(rcv*3+2)*F + j], g_v[(snd*3+2)*F + j]*gsv + gev*d2);
    }
}

// s += ds; v += dv; re-zero ds/dv for next phase/replay
__global__ void apply_k() {
    int idx = blockIdx.x * blockDim.x + threadIdx.x;
    if (idx >= NN*3*F) return;
    g_v[idx] += g_dv[idx];
    g_dv[idx] = 0.0f;
    if (idx < NN*F) { g_s[idx] += g_ds[idx]; g_ds[idx] = 0.0f; }
}

// Vn, dot(Uv,Vv), build m_in = [s, Vn]
__global__ void prep_k() {
    int idx = blockIdx.x * blockDim.x + threadIdx.x;
    if (idx >= NN*F) return;
    int n = idx >> 7, j = idx & 127;
    float u0 = g_Uv[(n*3+0)*F+j], u1 = g_Uv[(n*3+1)*F+j], u2 = g_Uv[(n*3+2)*F+j];
    float w0 = g_Vv[(n*3+0)*F+j], w1 = g_Vv[(n*3+1)*F+j], w2 = g_Vv[(n*3+2)*F+j];
    g_dot[idx] = u0*w0 + u1*w1 + u2*w2;
    g_min[n*256 + j]       = g_s[idx];
    g_min[n*256 + 128 + j] = sqrtf(w0*w0 + w1*w1 + w2*w2);
}

// s += a_ss + a_sv*dot ; v += a_vv*Uv ; write layer output
__global__ void final_k(float* __restrict__ out, int l) {
    int idx = blockIdx.x * blockDim.x + threadIdx.x;
    if (idx >= NN*F) return;
    int n = idx >> 7, j = idx & 127;
    float ass = g_m[(size_t)n*384 + j];
    float asv = g_m[(size_t)n*384 + 128 + j];
    float avv = g_m[(size_t)n*384 + 256 + j];
    float sv = g_s[idx] + ass + asv * g_dot[idx];
    g_s[idx] = sv;
    size_t ob = ((size_t)(l*NN + n) * 4) * F + j;
    out[ob] = sv;
#pragma unroll
    for (int d = 0; d < 3; d++) {
        float vv = g_v[(n*3+d)*F + j] + avv * g_Uv[(n*3+d)*F + j];
        g_v[(n*3+d)*F + j] = vv;
        out[ob + (size_t)(d+1)*F] = vv;
    }
}

// ---------------- host launcher ---------------------------------------------
static float* sym(const void* s) { void* p = nullptr; cudaGetSymbolAddress(&p, s); return (float*)p; }

extern "C" void kernel_launch(void* const* d_in, const int* in_sizes, int n_in,
                              void* d_out, int out_size) {
    (void)in_sizes; (void)n_in; (void)out_size;
    const float* atom_xyz = (const float*)d_in[0];
    const float* cell     = (const float*)d_in[1];
    const int*   nodes    = (const int*)  d_in[2];
    const int*   aedges   = (const int*)  d_in[3];
    const float* edisp    = (const float*)d_in[4];
    const float* Vflat    = (const float*)d_in[5];
    const float* Eflat    = (const float*)d_in[6];
    const float* emb      = (const float*)d_in[7];
    const float* potW     = (const float*)d_in[8];
    const float* potb     = (const float*)d_in[9];
    const float* iW1      = (const float*)d_in[10];
    const float* ib1      = (const float*)d_in[11];
    const float* iW2      = (const float*)d_in[12];
    const float* ib2      = (const float*)d_in[13];
    const float* vecw     = (const float*)d_in[14];
    const float* filtW    = (const float*)d_in[15];
    const float* filtb    = (const float*)d_in[16];
    const float* mW1      = (const float*)d_in[17];
    const float* mb1      = (const float*)d_in[18];
    const float* mW2      = (const float*)d_in[19];
    const float* mb2      = (const float*)d_in[20];
    const float* UW       = (const float*)d_in[21];
    const float* VW       = (const float*)d_in[22];
    const float* uW1      = (const float*)d_in[23];
    const float* ub1      = (const float*)d_in[24];
    const float* uW2      = (const float*)d_in[25];
    const float* ub2      = (const float*)d_in[26];
    float* out = (float*)d_out;

    float* ps   = sym(g_s);
    float* pv   = sym(g_v);
    float* pso  = sym(g_so);
    float* phid = sym(g_hid);
    float* pmin = sym(g_min);
    float* pm   = sym(g_m);
    float* pUv  = sym(g_Uv);
    float* pVv  = sym(g_Vv);
    float* pzb  = sym(g_zb);

    const int T = 256;
    const int NF_B   = (NN*F + T - 1) / T;      // 8192
    const int N3F_B  = (NN*3*F + T - 1) / T;    // 24576
    const int GEO_B  = (ETOT + T - 1) / T;      // 768

    reset_k<<<1, 1>>>();
    geom_k<<<GEO_B, T>>>(atom_xyz, cell, aedges, edisp);

    // init: s = silu(h @ iW1^T + ib1) @ iW2^T + ib2 ; v = E_flat * vec_w
    init_h_k<<<NF_B, T>>>(nodes, Vflat, emb, potW, potb);
    gemm_bias<1><<<dim3(2, NN/64), T>>>(pmin, iW1, ib1, phid, NN, F, 2*F);
    gemm_bias<0><<<dim3(2, NN/64), T>>>(phid, iW2, ib2, ps,   NN, F, F);
    init_v_k<<<N3F_B, T>>>(Eflat, vecw);

    for (int l = 0; l < NL; l++) {
        // so = silu(s @ mW1^T + mb1) @ mW2^T + mb2
        gemm_bias<1><<<dim3(2, NN/64), T>>>(ps,   mW1 + (size_t)l*F*F,    mb1 + l*F,   phid, NN, F,   F);
        gemm_bias<0><<<dim3(6, NN/64), T>>>(phid, mW2 + (size_t)l*3*F*F,  mb2 + l*3*F, pso,  NN, 3*F, F);
        // edge messages -> ds/dv (compacted active edges only)
        edge_k<<<ETOT/EPB, 128>>>(filtW + (size_t)l*3*F*KF, filtb + (size_t)l*3*F);
        apply_k<<<N3F_B, T>>>();
        // Uv = v @ UW^T ; Vv = v @ VW^T   (3N x 128)
        gemm_bias<0><<<dim3(2, 3*NN/64), T>>>(pv, UW + (size_t)l*F*F, pzb, pUv, 3*NN, F, F);
        gemm_bias<0><<<dim3(2, 3*NN/64), T>>>(pv, VW + (size_t)l*F*F, pzb, pVv, 3*NN, F, F);
        prep_k<<<NF_B, T>>>();
        // m = silu(m_in @ uW1^T + ub1) @ uW2^T + ub2
        gemm_bias<1><<<dim3(2, NN/64), T>>>(pmin, uW1 + (size_t)l*F*2*F, ub1 + l*F,   phid, NN, F,   2*F);
        gemm_bias<0><<<dim3(6, NN/64), T>>>(phid, uW2 + (size_t)l*3*F*F, ub2 + l*3*F, pm,   NN, 3*F, F);
        final_k<<<NF_B, T>>>(out, l);
    }
}

// round 2
// speedup vs baseline: 1.3811x; 1.3811x over previous
#include <cuda_runtime.h>
#include <math.h>

#define NB 4
#define NPER 4096
#define EPER 49152
#define NN (NB*NPER)        // 16384 nodes
#define ETOT (NB*EPER)      // 196608 edges
#define F 128
#define KF 20
#define NL 3
#define CUTF 5.0f
#define PIF 3.14159265358979323846f

// ---------------- scratch (device globals; zero-initialized) ----------------
__device__ float g_s  [NN*F];
__device__ float g_v  [NN*3*F];
__device__ float g_ds [NN*F];      // must be zero at start of each edge phase
__device__ float g_dv [NN*3*F];
__device__ float g_so [NN*3*F];
__device__ float g_hid[NN*F];
__device__ float g_min[NN*2*F];
__device__ float g_m  [NN*3*F];
__device__ float g_Uv [NN*3*F];
__device__ float g_Vv [NN*3*F];
__device__ float g_dot[NN*F];
__device__ float g_es [ETOT*KF];
__device__ float g_cut[ETOT];
__device__ float g_dir[ETOT*3];
__device__ int   g_send[ETOT];
__device__ int   g_recv[ETOT];
__device__ int   g_nact;
__device__ float g_zb[3*F];        // zero bias

// ------------- 128x128 tile SGEMM: C = act(A[M,K] @ W[N,K]^T + b) -----------
// 256 threads, 8x8 per thread, K-tile 8, k-major smem, register prefetch.
template<int ACT>
__global__ __launch_bounds__(256)
void gemm128(const float* __restrict__ A, const float* __restrict__ W,
             const float* __restrict__ bias, float* __restrict__ C,
             int M, int Nout, int Kin) {
    __shared__ float As[8][132];
    __shared__ float Ws[8][132];
    int tid = threadIdx.x;
    int tx = tid & 15, ty = tid >> 4;
    int m0 = blockIdx.y * 128, n0 = blockIdx.x * 128;
    int lrow  = tid >> 1;          // 0..127
    int lhalf = (tid & 1) * 4;     // 0 or 4
    const float* Aload = A + (size_t)(m0 + lrow) * Kin + lhalf;
    const float* Wload = W + (size_t)(n0 + lrow) * Kin + lhalf;

    float4 ra = *(const float4*)Aload;
    float4 rw = *(const float4*)Wload;

    float acc[8][8] = {};
    int ntiles = Kin >> 3;
    for (int kt = 0; kt < ntiles; kt++) {
        As[lhalf+0][lrow] = ra.x; As[lhalf+1][lrow] = ra.y;
        As[lhalf+2][lrow] = ra.z; As[lhalf+3][lrow] = ra.w;
        Ws[lhalf+0][lrow] = rw.x; Ws[lhalf+1][lrow] = rw.y;
        Ws[lhalf+2][lrow] = rw.z; Ws[lhalf+3][lrow] = rw.w;
        __syncthreads();
        if (kt + 1 < ntiles) {
            ra = *(const float4*)(Aload + (size_t)(kt+1)*8);
            rw = *(const float4*)(Wload + (size_t)(kt+1)*8);
        }
#pragma unroll
        for (int k = 0; k < 8; k++) {
            float a[8], w[8];
            *(float4*)(a)   = *(const float4*)&As[k][ty*8];
            *(float4*)(a+4) = *(const float4*)&As[k][ty*8+4];
            *(float4*)(w)   = *(const float4*)&Ws[k][tx*8];
            *(float4*)(w+4) = *(const float4*)&Ws[k][tx*8+4];
#pragma unroll
            for (int i = 0; i < 8; i++)
#pragma unroll
                for (int j = 0; j < 8; j++)
                    acc[i][j] += a[i] * w[j];
        }
        __syncthreads();
    }
    // epilogue: bias (+silu), vectorized stores
    float bv[8];
#pragma unroll
    for (int j = 0; j < 8; j++) bv[j] = bias[n0 + tx*8 + j];
#pragma unroll
    for (int i = 0; i < 8; i++) {
        int m = m0 + ty*8 + i;
        float o[8];
#pragma unroll
        for (int j = 0; j < 8; j++) {
            float val = acc[i][j] + bv[j];
            if (ACT) val = val / (1.0f + expf(-val));
            o[j] = val;
        }
        float* crow = C + (size_t)m * Nout + n0 + tx*8;
        *(float4*)(crow)     = *(float4*)(o);
        *(float4*)(crow + 4) = *(float4*)(o + 4);
    }
}

// ---------------- misc kernels ----------------------------------------------
__global__ void reset_k() { g_nact = 0; }

// geometry + active-edge compaction (cut==0 edges contribute exactly 0)
__global__ void geom_k(const float* __restrict__ xyz, const float* __restrict__ cell,
                       const int* __restrict__ aedges, const float* __restrict__ edisp) {
    int e = blockIdx.x * blockDim.x + threadIdx.x;
    if (e >= ETOT) return;
    int b = e / EPER;
    int snd = aedges[2*e]   + b * NPER;
    int rcv = aedges[2*e+1] + b * NPER;
    const float* cb = cell + b * 9;
    float c0 = edisp[3*e], c1 = edisp[3*e+1], c2 = edisp[3*e+2];
    float dx[3];
#pragma unroll
    for (int d = 0; d < 3; d++) {
        float disp = c0 * cb[d] + c1 * cb[3+d] + c2 * cb[6+d];
        dx[d] = xyz[3*rcv+d] - (xyz[3*snd+d] + disp);
    }
    float dist = sqrtf(dx[0]*dx[0] + dx[1]*dx[1] + dx[2]*dx[2]);
    if (dist < CUTF) {
        int p = atomicAdd(&g_nact, 1);
        g_send[p] = snd; g_recv[p] = rcv;
        float inv  = 1.0f / dist;
        float invm = 1.0f / fmaxf(dist, 1e-12f);
#pragma unroll
        for (int k = 0; k < KF; k++)
            g_es[p*KF+k] = sinf(dist * (float)(k+1) * (PIF/CUTF)) * inv;
        g_cut[p] = 0.5f * (cosf(PIF * dist / CUTF) + 1.0f);
        g_dir[3*p]   = dx[0]*invm;
        g_dir[3*p+1] = dx[1]*invm;
        g_dir[3*p+2] = dx[2]*invm;
    }
}

// h = [atom_emb[node], V*potW + potb]  -> g_min (N x 256)
__global__ void init_h_k(const int* __restrict__ nodes, const float* __restrict__ Vflat,
                         const float* __restrict__ emb, const float* __restrict__ potW,
                         const float* __restrict__ potb) {
    int idx = blockIdx.x * blockDim.x + threadIdx.x;
    if (idx >= NN*F) return;
    int n = idx >> 7, j = idx & 127;
    g_min[n*256 + j]       = emb[nodes[n]*F + j];
    g_min[n*256 + 128 + j] = Vflat[n] * potW[j] + potb[j];
}

// v = E_flat[:, :, None] * vec_w
__global__ void init_v_k(const float* __restrict__ Eflat, const float* __restrict__ vecw) {
    int idx = blockIdx.x * blockDim.x + threadIdx.x;
    if (idx >= NN*3*F) return;
    int r = idx >> 7, j = idx & 127;
    g_v[idx] = Eflat[r] * vecw[j];
}

// per-edge message + scatter (only active/compacted edges)
#define EPB 32
__global__ __launch_bounds__(128)
void edge_k(const float* __restrict__ fW, const float* __restrict__ fb) {
    int nact = g_nact;
    int e0 = blockIdx.x * EPB;
    if (e0 >= nact) return;
    __shared__ float sW[384*21];
    __shared__ float sb[384];
    for (int i = threadIdx.x; i < 384*KF; i += 128)
        sW[(i/KF)*21 + (i%KF)] = fW[i];
    for (int i = threadIdx.x; i < 384; i += 128) sb[i] = fb[i];
    __syncthreads();
    int j = threadIdx.x;
    int e1 = min(e0 + EPB, nact);
    for (int e = e0; e < e1; e++) {
        int snd = g_send[e], rcv = g_recv[e];
        float cutv = g_cut[e];
        float esr[KF];
#pragma unroll
        for (int k = 0; k < KF; k++) esr[k] = g_es[e*KF+k];
        float fw0 = sb[j], fw1 = sb[j+128], fw2 = sb[j+256];
#pragma unroll
        for (int k = 0; k < KF; k++) {
            fw0 += sW[j*21+k]       * esr[k];
            fw1 += sW[(j+128)*21+k] * esr[k];
            fw2 += sW[(j+256)*21+k] * esr[k];
        }
        const float* sop = g_so + (size_t)snd * 384;
        float gsv = fw0 * cutv * sop[j];
        float gev = fw1 * cutv * sop[j+128];
        float gns = fw2 * cutv * sop[j+256];
        atomicAdd(&g_ds[rcv*F + j], g_s[snd*F + j] * gns);
        float d0 = g_dir[3*e], d1 = g_dir[3*e+1], d2 = g_dir[3*e+2];
        atomicAdd(&g_dv[(rcv*3+0)*F + j], g_v[(snd*3+0)*F + j]*gsv + gev*d0);
        atomicAdd(&g_dv[(rcv*3+1)*F + j], g_v[(snd*3+1)*F + j]*gsv + gev*d1);
        atomicAdd(&g_dv[(rcv*3+2)*F + j], g_v[(snd*3+2)*F + j]*gsv + gev*d2);
    }
}

// s += ds; v += dv; re-zero ds/dv for next phase/replay
__global__ void apply_k() {
    int idx = blockIdx.x * blockDim.x + threadIdx.x;
    if (idx >= NN*3*F) return;
    g_v[idx] += g_dv[idx];
    g_dv[idx] = 0.0f;
    if (idx < NN*F) { g_s[idx] += g_ds[idx]; g_ds[idx] = 0.0f; }
}

// Vn, dot(Uv,Vv), build m_in = [s, Vn]
__global__ void prep_k() {
    int idx = blockIdx.x * blockDim.x + threadIdx.x;
    if (idx >= NN*F) return;
    int n = idx >> 7, j = idx & 127;
    float u0 = g_Uv[(n*3+0)*F+j], u1 = g_Uv[(n*3+1)*F+j], u2 = g_Uv[(n*3+2)*F+j];
    float w0 = g_Vv[(n*3+0)*F+j], w1 = g_Vv[(n*3+1)*F+j], w2 = g_Vv[(n*3+2)*F+j];
    g_dot[idx] = u0*w0 + u1*w1 + u2*w2;
    g_min[n*256 + j]       = g_s[idx];
    g_min[n*256 + 128 + j] = sqrtf(w0*w0 + w1*w1 + w2*w2);
}

// s += a_ss + a_sv*dot ; v += a_vv*Uv ; write layer output
__global__ void final_k(float* __restrict__ out, int l) {
    int idx = blockIdx.x * blockDim.x + threadIdx.x;
    if (idx >= NN*F) return;
    int n = idx >> 7, j = idx & 127;
    float ass = g_m[(size_t)n*384 + j];
    float asv = g_m[(size_t)n*384 + 128 + j];
    float avv = g_m[(size_t)n*384 + 256 + j];
    float sv = g_s[idx] + ass + asv * g_dot[idx];
    g_s[idx] = sv;
    size_t ob = ((size_t)(l*NN + n) * 4) * F + j;
    out[ob] = sv;
#pragma unroll
    for (int d = 0; d < 3; d++) {
        float vv = g_v[(n*3+d)*F + j] + avv * g_Uv[(n*3+d)*F + j];
        g_v[(n*3+d)*F + j] = vv;
        out[ob + (size_t)(d+1)*F] = vv;
    }
}

// ---------------- host launcher ---------------------------------------------
static float* sym(const void* s) { void* p = nullptr; cudaGetSymbolAddress(&p, s); return (float*)p; }

extern "C" void kernel_launch(void* const* d_in, const int* in_sizes, int n_in,
                              void* d_out, int out_size) {
    (void)in_sizes; (void)n_in; (void)out_size;
    const float* atom_xyz = (const float*)d_in[0];
    const float* cell     = (const float*)d_in[1];
    const int*   nodes    = (const int*)  d_in[2];
    const int*   aedges   = (const int*)  d_in[3];
    const float* edisp    = (const float*)d_in[4];
    const float* Vflat    = (const float*)d_in[5];
    const float* Eflat    = (const float*)d_in[6];
    const float* emb      = (const float*)d_in[7];
    const float* potW     = (const float*)d_in[8];
    const float* potb     = (const float*)d_in[9];
    const float* iW1      = (const float*)d_in[10];
    const float* ib1      = (const float*)d_in[11];
    const float* iW2      = (const float*)d_in[12];
    const float* ib2      = (const float*)d_in[13];
    const float* vecw     = (const float*)d_in[14];
    const float* filtW    = (const float*)d_in[15];
    const float* filtb    = (const float*)d_in[16];
    const float* mW1      = (const float*)d_in[17];
    const float* mb1      = (const float*)d_in[18];
    const float* mW2      = (const float*)d_in[19];
    const float* mb2      = (const float*)d_in[20];
    const float* UW       = (const float*)d_in[21];
    const float* VW       = (const float*)d_in[22];
    const float* uW1      = (const float*)d_in[23];
    const float* ub1      = (const float*)d_in[24];
    const float* uW2      = (const float*)d_in[25];
    const float* ub2      = (const float*)d_in[26];
    float* out = (float*)d_out;

    float* ps   = sym(g_s);
    float* pv   = sym(g_v);
    float* pso  = sym(g_so);
    float* phid = sym(g_hid);
    float* pmin = sym(g_min);
    float* pm   = sym(g_m);
    float* pUv  = sym(g_Uv);
    float* pVv  = sym(g_Vv);
    float* pzb  = sym(g_zb);

    const int T = 256;
    const int NF_B   = (NN*F + T - 1) / T;      // 8192
    const int N3F_B  = (NN*3*F + T - 1) / T;    // 24576
    const int GEO_B  = (ETOT + T - 1) / T;      // 768

    reset_k<<<1, 1>>>();
    geom_k<<<GEO_B, T>>>(atom_xyz, cell, aedges, edisp);

    // init: s = silu(h @ iW1^T + ib1) @ iW2^T + ib2 ; v = E_flat * vec_w
    init_h_k<<<NF_B, T>>>(nodes, Vflat, emb, potW, potb);
    gemm128<1><<<dim3(1, NN/128), T>>>(pmin, iW1, ib1, phid, NN, F, 2*F);
    gemm128<0><<<dim3(1, NN/128), T>>>(phid, iW2, ib2, ps,   NN, F, F);
    init_v_k<<<N3F_B, T>>>(Eflat, vecw);

    for (int l = 0; l < NL; l++) {
        // so = silu(s @ mW1^T + mb1) @ mW2^T + mb2
        gemm128<1><<<dim3(1, NN/128), T>>>(ps,   mW1 + (size_t)l*F*F,    mb1 + l*F,   phid, NN, F,   F);
        gemm128<0><<<dim3(3, NN/128), T>>>(phid, mW2 + (size_t)l*3*F*F,  mb2 + l*3*F, pso,  NN, 3*F, F);
        // edge messages -> ds/dv (compacted active edges only)
        edge_k<<<ETOT/EPB, 128>>>(filtW + (size_t)l*3*F*KF, filtb + (size_t)l*3*F);
        apply_k<<<N3F_B, T>>>();
        // Uv = v @ UW^T ; Vv = v @ VW^T   (3N x 128)
        gemm128<0><<<dim3(1, 3*NN/128), T>>>(pv, UW + (size_t)l*F*F, pzb, pUv, 3*NN, F, F);
        gemm128<0><<<dim3(1, 3*NN/128), T>>>(pv, VW + (size_t)l*F*F, pzb, pVv, 3*NN, F, F);
        prep_k<<<NF_B, T>>>();
        // m = silu(m_in @ uW1^T + ub1) @ uW2^T + ub2
        gemm128<1><<<dim3(1, NN/128), T>>>(pmin, uW1 + (size_t)l*F*2*F, ub1 + l*F,   phid, NN, F,   2*F);
        gemm128<0><<<dim3(3, NN/128), T>>>(phid, uW2 + (size_t)l*3*F*F, ub2 + l*3*F, pm,   NN, 3*F, F);
        final_k<<<NF_B, T>>>(out, l);
    }
}

// round 3
// speedup vs baseline: 1.4072x; 1.0189x over previous
#include <cuda_runtime.h>
#include <math.h>

#define NB 4
#define NPER 4096
#define EPER 49152
#define NN (NB*NPER)        // 16384 nodes
#define ETOT (NB*EPER)      // 196608 edges
#define F 128
#define KF 20
#define NL 3
#define CUTF 5.0f
#define PIF 3.14159265358979323846f

// ---------------- scratch (device globals; zero-initialized) ----------------
__device__ float g_s  [NN*F];
__device__ float g_v  [NN*3*F];
__device__ float g_ds [NN*F];
__device__ float g_dv [NN*3*F];
__device__ float g_so [NN*3*F];
__device__ float g_hid[NN*F];
__device__ float g_min[NN*2*F];
__device__ float g_m  [NN*3*F];
__device__ float g_UVo[NN*3*256];   // [row=3n+d][0:128)=Uv, [128:256)=Vv
__device__ float g_UVW[NL*256*F];   // packed [l][U rows|V rows][K]
__device__ float g_dot[NN*F];
__device__ float g_es [ETOT*KF];
__device__ float g_cut[ETOT];
__device__ float g_dir[ETOT*3];
__device__ int   g_send[ETOT];
__device__ int   g_recv[ETOT];
__device__ int   g_nact;
__device__ float g_zb[3*F];         // zero bias

// ------- 64x128 tile SGEMM: C = act(A[M,K] @ W[N,K]^T + b), double-buffered -
// 256 threads, 4x8 per thread (w split into cols tx*4 and 64+tx*4).
template<int ACT>
__global__ __launch_bounds__(256)
void gemm64(const float* __restrict__ A, const float* __restrict__ W,
            const float* __restrict__ bias, float* __restrict__ C,
            int M, int Nout, int Kin) {
    __shared__ float As[2][8][68];
    __shared__ float Ws[2][8][132];
    int tid = threadIdx.x;
    int tx = tid & 15, ty = tid >> 4;
    int m0 = blockIdx.y * 64, n0 = blockIdx.x * 128;

    int arow = tid >> 2, ak = (tid & 3) * 2;   // 64 rows x 8k via float2
    int wrow = tid >> 1, wk = (tid & 1) * 4;   // 128 rows x 8k via float4
    const float* Aload = A + (size_t)(m0 + arow) * Kin + ak;
    const float* Wload = W + (size_t)(n0 + wrow) * Kin + wk;

    float2 ra = *(const float2*)Aload;
    float4 rw = *(const float4*)Wload;

    float acc[4][8] = {};
    int nt = Kin >> 3;

    // stage tile 0
    As[0][ak][arow] = ra.x; As[0][ak+1][arow] = ra.y;
    Ws[0][wk][wrow] = rw.x; Ws[0][wk+1][wrow] = rw.y;
    Ws[0][wk+2][wrow] = rw.z; Ws[0][wk+3][wrow] = rw.w;
    __syncthreads();
    if (nt > 1) {
        ra = *(const float2*)(Aload + 8);
        rw = *(const float4*)(Wload + 8);
    }

    for (int kt = 0; kt < nt; kt++) {
        int nb = (kt + 1) & 1;
        if (kt + 1 < nt) {
            As[nb][ak][arow] = ra.x; As[nb][ak+1][arow] = ra.y;
            Ws[nb][wk][wrow] = rw.x; Ws[nb][wk+1][wrow] = rw.y;
            Ws[nb][wk+2][wrow] = rw.z; Ws[nb][wk+3][wrow] = rw.w;
        }
        if (kt + 2 < nt) {
            ra = *(const float2*)(Aload + (size_t)(kt+2)*8);
            rw = *(const float4*)(Wload + (size_t)(kt+2)*8);
        }
        int cb = kt & 1;
#pragma unroll
        for (int k = 0; k < 8; k++) {
            float a[4], w[8];
            *(float4*)a     = *(const float4*)&As[cb][k][ty*4];
            *(float4*)(w)   = *(const float4*)&Ws[cb][k][tx*4];
            *(float4*)(w+4) = *(const float4*)&Ws[cb][k][64 + tx*4];
#pragma unroll
            for (int i = 0; i < 4; i++)
#pragma unroll
                for (int j = 0; j < 8; j++)
                    acc[i][j] += a[i] * w[j];
        }
        __syncthreads();
    }

    float bv[8];
#pragma unroll
    for (int j = 0; j < 4; j++) {
        bv[j]   = bias[n0 + tx*4 + j];
        bv[4+j] = bias[n0 + 64 + tx*4 + j];
    }
#pragma unroll
    for (int i = 0; i < 4; i++) {
        int m = m0 + ty*4 + i;
        float o[8];
#pragma unroll
        for (int j = 0; j < 8; j++) {
            float val = acc[i][j] + bv[j];
            if (ACT) val = val / (1.0f + expf(-val));
            o[j] = val;
        }
        float* crow = C + (size_t)m * Nout + n0;
        *(float4*)(crow + tx*4)      = *(float4*)(o);
        *(float4*)(crow + 64 + tx*4) = *(float4*)(o + 4);
    }
}

// ---------------- misc kernels ----------------------------------------------
__global__ void reset_k() { g_nact = 0; }

__global__ void pack_uv_k(const float* __restrict__ UW, const float* __restrict__ VW) {
    int idx = blockIdx.x * blockDim.x + threadIdx.x;
    if (idx >= NL*2*F*F) return;
    int l = idx / (2*F*F);
    int r = (idx / F) % (2*F);
    int k = idx % F;
    g_UVW[idx] = (r < F) ? UW[(size_t)l*F*F + r*F + k]
                         : VW[(size_t)l*F*F + (r-F)*F + k];
}

// geometry + active-edge compaction (cut==0 edges contribute exactly 0)
__global__ void geom_k(const float* __restrict__ xyz, const float* __restrict__ cell,
                       const int* __restrict__ aedges, const float* __restrict__ edisp) {
    int e = blockIdx.x * blockDim.x + threadIdx.x;
    if (e >= ETOT) return;
    int b = e / EPER;
    int snd = aedges[2*e]   + b * NPER;
    int rcv = aedges[2*e+1] + b * NPER;
    const float* cb = cell + b * 9;
    float c0 = edisp[3*e], c1 = edisp[3*e+1], c2 = edisp[3*e+2];
    float dx[3];
#pragma unroll
    for (int d = 0; d < 3; d++) {
        float disp = c0 * cb[d] + c1 * cb[3+d] + c2 * cb[6+d];
        dx[d] = xyz[3*rcv+d] - (xyz[3*snd+d] + disp);
    }
    float dist = sqrtf(dx[0]*dx[0] + dx[1]*dx[1] + dx[2]*dx[2]);
    if (dist < CUTF) {
        int p = atomicAdd(&g_nact, 1);
        g_send[p] = snd; g_recv[p] = rcv;
        float inv  = 1.0f / dist;
        float invm = 1.0f / fmaxf(dist, 1e-12f);
#pragma unroll
        for (int k = 0; k < KF; k++)
            g_es[p*KF+k] = sinf(dist * (float)(k+1) * (PIF/CUTF)) * inv;
        g_cut[p] = 0.5f * (cosf(PIF * dist / CUTF) + 1.0f);
        g_dir[3*p]   = dx[0]*invm;
        g_dir[3*p+1] = dx[1]*invm;
        g_dir[3*p+2] = dx[2]*invm;
    }
}

// h = [atom_emb[node], V*potW + potb]  -> g_min (N x 256)
__global__ void init_h_k(const int* __restrict__ nodes, const float* __restrict__ Vflat,
                         const float* __restrict__ emb, const float* __restrict__ potW,
                         const float* __restrict__ potb) {
    int idx = blockIdx.x * blockDim.x + threadIdx.x;
    if (idx >= NN*F) return;
    int n = idx >> 7, j = idx & 127;
    g_min[n*256 + j]       = emb[nodes[n]*F + j];
    g_min[n*256 + 128 + j] = Vflat[n] * potW[j] + potb[j];
}

// v = E_flat[:, :, None] * vec_w
__global__ void init_v_k(const float* __restrict__ Eflat, const float* __restrict__ vecw) {
    int idx = blockIdx.x * blockDim.x + threadIdx.x;
    if (idx >= NN*3*F) return;
    int r = idx >> 7, j = idx & 127;
    g_v[idx] = Eflat[r] * vecw[j];
}

// per-edge message + scatter (only active/compacted edges)
#define EPB 32
__global__ __launch_bounds__(128)
void edge_k(const float* __restrict__ fW, const float* __restrict__ fb) {
    int nact = g_nact;
    int e0 = blockIdx.x * EPB;
    if (e0 >= nact) return;
    __shared__ float sW[384*21];
    __shared__ float sb[384];
    for (int i = threadIdx.x; i < 384*KF; i += 128)
        sW[(i/KF)*21 + (i%KF)] = fW[i];
    for (int i = threadIdx.x; i < 384; i += 128) sb[i] = fb[i];
    __syncthreads();
    int j = threadIdx.x;
    int e1 = min(e0 + EPB, nact);
    for (int e = e0; e < e1; e++) {
        int snd = g_send[e], rcv = g_recv[e];
        float cutv = g_cut[e];
        float esr[KF];
#pragma unroll
        for (int k = 0; k < KF; k++) esr[k] = g_es[e*KF+k];
        float fw0 = sb[j], fw1 = sb[j+128], fw2 = sb[j+256];
#pragma unroll
        for (int k = 0; k < KF; k++) {
            fw0 += sW[j*21+k]       * esr[k];
            fw1 += sW[(j+128)*21+k] * esr[k];
            fw2 += sW[(j+256)*21+k] * esr[k];
        }
        const float* sop = g_so + (size_t)snd * 384;
        float gsv = fw0 * cutv * sop[j];
        float gev = fw1 * cutv * sop[j+128];
        float gns = fw2 * cutv * sop[j+256];
        atomicAdd(&g_ds[rcv*F + j], g_s[snd*F + j] * gns);
        float d0 = g_dir[3*e], d1 = g_dir[3*e+1], d2 = g_dir[3*e+2];
        atomicAdd(&g_dv[(rcv*3+0)*F + j], g_v[(snd*3+0)*F + j]*gsv + gev*d0);
        atomicAdd(&g_dv[(rcv*3+1)*F + j], g_v[(snd*3+1)*F + j]*gsv + gev*d1);
        atomicAdd(&g_dv[(rcv*3+2)*F + j], g_v[(snd*3+2)*F + j]*gsv + gev*d2);
    }
}

// s += ds; v += dv; re-zero ds/dv for next phase/replay
__global__ void apply_k() {
    int idx = blockIdx.x * blockDim.x + threadIdx.x;
    if (idx >= NN*3*F) return;
    g_v[idx] += g_dv[idx];
    g_dv[idx] = 0.0f;
    if (idx < NN*F) { g_s[idx] += g_ds[idx]; g_ds[idx] = 0.0f; }
}

// Vn, dot(Uv,Vv), build m_in = [s, Vn]
__global__ void prep_k() {
    int idx = blockIdx.x * blockDim.x + threadIdx.x;
    if (idx >= NN*F) return;
    int n = idx >> 7, j = idx & 127;
    float u0 = g_UVo[(size_t)(n*3+0)*256 + j];
    float u1 = g_UVo[(size_t)(n*3+1)*256 + j];
    float u2 = g_UVo[(size_t)(n*3+2)*256 + j];
    float w0 = g_UVo[(size_t)(n*3+0)*256 + 128 + j];
    float w1 = g_UVo[(size_t)(n*3+1)*256 + 128 + j];
    float w2 = g_UVo[(size_t)(n*3+2)*256 + 128 + j];
    g_dot[idx] = u0*w0 + u1*w1 + u2*w2;
    g_min[n*256 + j]       = g_s[idx];
    g_min[n*256 + 128 + j] = sqrtf(w0*w0 + w1*w1 + w2*w2);
}

// s += a_ss + a_sv*dot ; v += a_vv*Uv ; write layer output
__global__ void final_k(float* __restrict__ out, int l) {
    int idx = blockIdx.x * blockDim.x + threadIdx.x;
    if (idx >= NN*F) return;
    int n = idx >> 7, j = idx & 127;
    float ass = g_m[(size_t)n*384 + j];
    float asv = g_m[(size_t)n*384 + 128 + j];
    float avv = g_m[(size_t)n*384 + 256 + j];
    float sv = g_s[idx] + ass + asv * g_dot[idx];
    g_s[idx] = sv;
    size_t ob = ((size_t)(l*NN + n) * 4) * F + j;
    out[ob] = sv;
#pragma unroll
    for (int d = 0; d < 3; d++) {
        float uv = g_UVo[(size_t)(n*3+d)*256 + j];
        float vv = g_v[(n*3+d)*F + j] + avv * uv;
        g_v[(n*3+d)*F + j] = vv;
        out[ob + (size_t)(d+1)*F] = vv;
    }
}

// ---------------- host launcher ---------------------------------------------
static float* sym(const void* s) { void* p = nullptr; cudaGetSymbolAddress(&p, s); return (float*)p; }

extern "C" void kernel_launch(void* const* d_in, const int* in_sizes, int n_in,
                              void* d_out, int out_size) {
    (void)in_sizes; (void)n_in; (void)out_size;
    const float* atom_xyz = (const float*)d_in[0];
    const float* cell     = (const float*)d_in[1];
    const int*   nodes    = (const int*)  d_in[2];
    const int*   aedges   = (const int*)  d_in[3];
    const float* edisp    = (const float*)d_in[4];
    const float* Vflat    = (const float*)d_in[5];
    const float* Eflat    = (const float*)d_in[6];
    const float* emb      = (const float*)d_in[7];
    const float* potW     = (const float*)d_in[8];
    const float* potb     = (const float*)d_in[9];
    const float* iW1      = (const float*)d_in[10];
    const float* ib1      = (const float*)d_in[11];
    const float* iW2      = (const float*)d_in[12];
    const float* ib2      = (const float*)d_in[13];
    const float* vecw     = (const float*)d_in[14];
    const float* filtW    = (const float*)d_in[15];
    const float* filtb    = (const float*)d_in[16];
    const float* mW1      = (const float*)d_in[17];
    const float* mb1      = (const float*)d_in[18];
    const float* mW2      = (const float*)d_in[19];
    const float* mb2      = (const float*)d_in[20];
    const float* UW       = (const float*)d_in[21];
    const float* VW       = (const float*)d_in[22];
    const float* uW1      = (const float*)d_in[23];
    const float* ub1      = (const float*)d_in[24];
    const float* uW2      = (const float*)d_in[25];
    const float* ub2      = (const float*)d_in[26];
    float* out = (float*)d_out;

    float* ps   = sym(g_s);
    float* pv   = sym(g_v);
    float* pso  = sym(g_so);
    float* phid = sym(g_hid);
    float* pmin = sym(g_min);
    float* pm   = sym(g_m);
    float* pUVo = sym(g_UVo);
    float* pUVW = sym(g_UVW);
    float* pzb  = sym(g_zb);

    const int T = 256;
    const int NF_B   = (NN*F + T - 1) / T;
    const int N3F_B  = (NN*3*F + T - 1) / T;
    const int GEO_B  = (ETOT + T - 1) / T;

    reset_k<<<1, 1>>>();
    geom_k<<<GEO_B, T>>>(atom_xyz, cell, aedges, edisp);
    pack_uv_k<<<(NL*2*F*F + T - 1)/T, T>>>(UW, VW);

    init_h_k<<<NF_B, T>>>(nodes, Vflat, emb, potW, potb);
    gemm64<1><<<dim3(1, NN/64), T>>>(pmin, iW1, ib1, phid, NN, F, 2*F);
    gemm64<0><<<dim3(1, NN/64), T>>>(phid, iW2, ib2, ps,   NN, F, F);
    init_v_k<<<N3F_B, T>>>(Eflat, vecw);

    for (int l = 0; l < NL; l++) {
        gemm64<1><<<dim3(1, NN/64), T>>>(ps,   mW1 + (size_t)l*F*F,    mb1 + l*F,   phid, NN, F,   F);
        gemm64<0><<<dim3(3, NN/64), T>>>(phid, mW2 + (size_t)l*3*F*F,  mb2 + l*3*F, pso,  NN, 3*F, F);
        edge_k<<<ETOT/EPB, 128>>>(filtW + (size_t)l*3*F*KF, filtb + (size_t)l*3*F);
        apply_k<<<N3F_B, T>>>();
        // [Uv | Vv] = v @ [UW|VW]^T  (3N x 256, packed weights)
        gemm64<0><<<dim3(2, 3*NN/64), T>>>(pv, pUVW + (size_t)l*256*F, pzb, pUVo, 3*NN, 256, F);
        prep_k<<<NF_B, T>>>();
        gemm64<1><<<dim3(1, NN/64), T>>>(pmin, uW1 + (size_t)l*F*2*F, ub1 + l*F,   phid, NN, F,   2*F);
        gemm64<0><<<dim3(3, NN/64), T>>>(phid, uW2 + (size_t)l*3*F*F, ub2 + l*3*F, pm,   NN, 3*F, F);
        final_k<<<NF_B, T>>>(out, l);
    }
}

// round 5
// speedup vs baseline: 1.9184x; 1.3633x over previous
#include <cuda_runtime.h>
#include <cuda_bf16.h>
#include <math.h>
#include <stdint.h>

#define NB 4
#define NPER 4096
#define EPER 49152
#define NN (NB*NPER)        // 16384 nodes
#define ETOT (NB*EPER)      // 196608 edges
#define F 128
#define KF 20
#define NL 3
#define CUTF 5.0f
#define PIF 3.14159265358979323846f

// ---------------- scratch (device globals; zero-initialized) ----------------
__device__ __align__(16) float g_s  [NN*F];
__device__ __align__(16) float g_v  [NN*3*F];
__device__ __align__(16) float g_ds [NN*F];
__device__ __align__(16) float g_dv [NN*3*F];
__device__ __align__(16) float g_so [NN*3*F];
__device__ __align__(16) float g_hid[NN*F];
__device__ __align__(16) float g_min[NN*2*F];
__device__ __align__(16) float g_m  [NN*3*F];
__device__ __align__(16) float g_UVo[NN*3*256];   // [row=3n+d][0:128)=Uv, [128:256)=Vv
__device__ __align__(16) float g_UVW[NL*256*F];   // packed [l][U rows|V rows][K]
__device__ __align__(16) float g_dot[NN*F];
__device__ __align__(16) float g_es [ETOT*KF];
__device__ float g_cut[ETOT];
__device__ float g_dir[ETOT*3];
__device__ int   g_send[ETOT];
__device__ int   g_recv[ETOT];
__device__ int   g_nact;
__device__ float g_zb[3*F];         // zero bias

// =================== mma.sync helpers (sm_80+ path, valid on sm_103) ========
__device__ __forceinline__ uint32_t smem_u32(const void* p) {
    uint32_t a;
    asm("{ .reg .u64 t; cvta.to.shared.u64 t, %1; cvt.u32.u64 %0, t; }"
        : "=r"(a) : "l"(p));
    return a;
}

__device__ __forceinline__ void ldsm4(uint32_t* r, uint32_t addr) {
    asm volatile("ldmatrix.sync.aligned.m8n8.x4.shared.b16 {%0,%1,%2,%3}, [%4];"
        : "=r"(r[0]), "=r"(r[1]), "=r"(r[2]), "=r"(r[3]) : "r"(addr));
}

__device__ __forceinline__ void mma_bf16(float* c, const uint32_t* a, const uint32_t* b) {
    asm volatile("mma.sync.aligned.m16n8k16.row.col.f32.bf16.bf16.f32 "
        "{%0,%1,%2,%3}, {%4,%5,%6,%7}, {%8,%9}, {%0,%1,%2,%3};"
        : "+f"(c[0]), "+f"(c[1]), "+f"(c[2]), "+f"(c[3])
        : "r"(a[0]), "r"(a[1]), "r"(a[2]), "r"(a[3]), "r"(b[0]), "r"(b[1]));
}

// split fp32 -> hi bf16 + residual bf16, store 4 elements (8B each array)
__device__ __forceinline__ void store_split(__nv_bfloat16* hi, __nv_bfloat16* lo, float4 v) {
    __nv_bfloat16 h0 = __float2bfloat16(v.x), h1 = __float2bfloat16(v.y);
    __nv_bfloat16 h2 = __float2bfloat16(v.z), h3 = __float2bfloat16(v.w);
    __nv_bfloat16 l0 = __float2bfloat16(v.x - __bfloat162float(h0));
    __nv_bfloat16 l1 = __float2bfloat16(v.y - __bfloat162float(h1));
    __nv_bfloat16 l2 = __float2bfloat16(v.z - __bfloat162float(h2));
    __nv_bfloat16 l3 = __float2bfloat16(v.w - __bfloat162float(h3));
    uint2 H, L;
    H.x = ((uint32_t)__bfloat16_as_ushort(h1) << 16) | __bfloat16_as_ushort(h0);
    H.y = ((uint32_t)__bfloat16_as_ushort(h3) << 16) | __bfloat16_as_ushort(h2);
    L.x = ((uint32_t)__bfloat16_as_ushort(l1) << 16) | __bfloat16_as_ushort(l0);
    L.y = ((uint32_t)__bfloat16_as_ushort(l3) << 16) | __bfloat16_as_ushort(l2);
    *(uint2*)hi = H;
    *(uint2*)lo = L;
}

// ========== split-bf16 HMMA GEMM: C = act(A[M,K] @ W[N,K]^T + b) ===========
// 128x128 CTA tile, 8 warps (2x4), warp tile 64x32 (4x4 m16n8k16 tiles),
// K chunks of 128. 3 split passes fused per k-step: Ah*Bh + Ah*Bl + Al*Bh.
#define LDA 136
#define ASZ (128*LDA)
#define GSMEM (4*ASZ*2)

template<int ACT>
__global__ __launch_bounds__(256)
void gemm_mma(const float* __restrict__ A, const float* __restrict__ W,
              const float* __restrict__ bias, float* __restrict__ C,
              int Nout, int Kin) {
    extern __shared__ __nv_bfloat16 sm[];
    __nv_bfloat16* Ah = sm;
    __nv_bfloat16* Al = sm + ASZ;
    __nv_bfloat16* Bh = sm + 2*ASZ;
    __nv_bfloat16* Bl = sm + 3*ASZ;
    int tid = threadIdx.x, lane = tid & 31, w = tid >> 5;
    int wr = w >> 2, wc = w & 3;
    int m0 = blockIdx.y * 128, n0 = blockIdx.x * 128;
    uint32_t aAh = smem_u32(Ah), aAl = smem_u32(Al);
    uint32_t aBh = smem_u32(Bh), aBl = smem_u32(Bl);

    float acc[4][4][4] = {};
    int nch = Kin >> 7;
    for (int ch = 0; ch < nch; ch++) {
        int kc = ch << 7;
        if (ch) __syncthreads();
#pragma unroll 4
        for (int g = tid; g < 4096; g += 256) {
            int row = g >> 5, col = (g & 31) << 2;
            float4 av = *(const float4*)(A + (size_t)(m0 + row) * Kin + kc + col);
            float4 wv = *(const float4*)(W + (size_t)(n0 + row) * Kin + kc + col);
            store_split(Ah + row*LDA + col, Al + row*LDA + col, av);
            store_split(Bh + row*LDA + col, Bl + row*LDA + col, wv);
        }
        __syncthreads();

        int arow  = lane & 15;
        int acol  = (lane >> 4) * 8;
        int bmat  = lane >> 3;
        int brow  = (bmat >> 1) * 8 + (lane & 7);
        int bcol  = (bmat & 1) * 8;
#pragma unroll
        for (int ks = 0; ks < 8; ks++) {
            int k0 = ks * 16;
            uint32_t ah[4][4], al[4][4], bh[2][4], bl[2][4];
#pragma unroll
            for (int mi = 0; mi < 4; mi++) {
                uint32_t off = (uint32_t)((wr*64 + mi*16 + arow) * LDA + k0 + acol) * 2;
                ldsm4(ah[mi], aAh + off);
                ldsm4(al[mi], aAl + off);
            }
#pragma unroll
            for (int p = 0; p < 2; p++) {
                uint32_t off = (uint32_t)((wc*32 + p*16 + brow) * LDA + k0 + bcol) * 2;
                ldsm4(bh[p], aBh + off);
                ldsm4(bl[p], aBl + off);
            }
#pragma unroll
            for (int mi = 0; mi < 4; mi++)
#pragma unroll
                for (int ni = 0; ni < 4; ni++) {
                    const uint32_t* BH = &bh[ni >> 1][(ni & 1) * 2];
                    const uint32_t* BL = &bl[ni >> 1][(ni & 1) * 2];
                    mma_bf16(acc[mi][ni], ah[mi], BH);
                    mma_bf16(acc[mi][ni], ah[mi], BL);
                    mma_bf16(acc[mi][ni], al[mi], BH);
                }
        }
    }

    // epilogue: c0,c1 at (row, col..col+1), c2,c3 at (row+8, ...)
#pragma unroll
    for (int ni = 0; ni < 4; ni++) {
        int c = wc*32 + ni*8 + (lane & 3) * 2;
        float b0 = bias[n0 + c], b1 = bias[n0 + c + 1];
#pragma unroll
        for (int mi = 0; mi < 4; mi++) {
            int r0 = m0 + wr*64 + mi*16 + (lane >> 2);
            float o0 = acc[mi][ni][0] + b0;
            float o1 = acc[mi][ni][1] + b1;
            float o2 = acc[mi][ni][2] + b0;
            float o3 = acc[mi][ni][3] + b1;
            if (ACT) {
                o0 = o0 / (1.0f + expf(-o0));
                o1 = o1 / (1.0f + expf(-o1));
                o2 = o2 / (1.0f + expf(-o2));
                o3 = o3 / (1.0f + expf(-o3));
            }
            float2 p0 = make_float2(o0, o1), p1 = make_float2(o2, o3);
            *(float2*)(C + (size_t)r0 * Nout + n0 + c)       = p0;
            *(float2*)(C + (size_t)(r0 + 8) * Nout + n0 + c) = p1;
        }
    }
}

// ---------------- misc kernels ----------------------------------------------
__global__ void reset_k() { g_nact = 0; }

__global__ void pack_uv_k(const float* __restrict__ UW, const float* __restrict__ VW) {
    int idx = blockIdx.x * blockDim.x + threadIdx.x;
    if (idx >= NL*2*F*F) return;
    int l = idx / (2*F*F);
    int r = (idx / F) % (2*F);
    int k = idx % F;
    g_UVW[idx] = (r < F) ? UW[(size_t)l*F*F + r*F + k]
                         : VW[(size_t)l*F*F + (r-F)*F + k];
}

__global__ void geom_k(const float* __restrict__ xyz, const float* __restrict__ cell,
                       const int* __restrict__ aedges, const float* __restrict__ edisp) {
    int e = blockIdx.x * blockDim.x + threadIdx.x;
    if (e >= ETOT) return;
    int b = e / EPER;
    int snd = aedges[2*e]   + b * NPER;
    int rcv = aedges[2*e+1] + b * NPER;
    const float* cb = cell + b * 9;
    float c0 = edisp[3*e], c1 = edisp[3*e+1], c2 = edisp[3*e+2];
    float dx[3];
#pragma unroll
    for (int d = 0; d < 3; d++) {
        float disp = c0 * cb[d] + c1 * cb[3+d] + c2 * cb[6+d];
        dx[d] = xyz[3*rcv+d] - (xyz[3*snd+d] + disp);
    }
    float dist = sqrtf(dx[0]*dx[0] + dx[1]*dx[1] + dx[2]*dx[2]);
    if (dist < CUTF) {
        int p = atomicAdd(&g_nact, 1);
        g_send[p] = snd; g_recv[p] = rcv;
        float inv  = 1.0f / dist;
        float invm = 1.0f / fmaxf(dist, 1e-12f);
#pragma unroll
        for (int k = 0; k < KF; k++)
            g_es[p*KF+k] = sinf(dist * (float)(k+1) * (PIF/CUTF)) * inv;
        g_cut[p] = 0.5f * (cosf(PIF * dist / CUTF) + 1.0f);
        g_dir[3*p]   = dx[0]*invm;
        g_dir[3*p+1] = dx[1]*invm;
        g_dir[3*p+2] = dx[2]*invm;
    }
}

__global__ void init_h_k(const int* __restrict__ nodes, const float* __restrict__ Vflat,
                         const float* __restrict__ emb, const float* __restrict__ potW,
                         const float* __restrict__ potb) {
    int idx = blockIdx.x * blockDim.x + threadIdx.x;
    if (idx >= NN*F) return;
    int n = idx >> 7, j = idx & 127;
    g_min[n*256 + j]       = emb[nodes[n]*F + j];
    g_min[n*256 + 128 + j] = Vflat[n] * potW[j] + potb[j];
}

__global__ void init_v_k(const float* __restrict__ Eflat, const float* __restrict__ vecw) {
    int idx = blockIdx.x * blockDim.x + threadIdx.x;
    if (idx >= NN*3*F) return;
    int r = idx >> 7, j = idx & 127;
    g_v[idx] = Eflat[r] * vecw[j];
}

#define EPB 32
__global__ __launch_bounds__(128)
void edge_k(const float* __restrict__ fW, const float* __restrict__ fb) {
    int nact = g_nact;
    int e0 = blockIdx.x * EPB;
    if (e0 >= nact) return;
    __shared__ float sW[384*21];
    __shared__ float sb[384];
    for (int i = threadIdx.x; i < 384*KF; i += 128)
        sW[(i/KF)*21 + (i%KF)] = fW[i];
    for (int i = threadIdx.x; i < 384; i += 128) sb[i] = fb[i];
    __syncthreads();
    int j = threadIdx.x;
    int e1 = min(e0 + EPB, nact);
    for (int e = e0; e < e1; e++) {
        int snd = g_send[e], rcv = g_recv[e];
        float cutv = g_cut[e];
        float esr[KF];
#pragma unroll
        for (int k = 0; k < KF; k++) esr[k] = g_es[e*KF+k];
        float fw0 = sb[j], fw1 = sb[j+128], fw2 = sb[j+256];
#pragma unroll
        for (int k = 0; k < KF; k++) {
            fw0 += sW[j*21+k]       * esr[k];
            fw1 += sW[(j+128)*21+k] * esr[k];
            fw2 += sW[(j+256)*21+k] * esr[k];
        }
        const float* sop = g_so + (size_t)snd * 384;
        float gsv = fw0 * cutv * sop[j];
        float gev = fw1 * cutv * sop[j+128];
        float gns = fw2 * cutv * sop[j+256];
        atomicAdd(&g_ds[rcv*F + j], g_s[snd*F + j] * gns);
        float d0 = g_dir[3*e], d1 = g_dir[3*e+1], d2 = g_dir[3*e+2];
        atomicAdd(&g_dv[(rcv*3+0)*F + j], g_v[(snd*3+0)*F + j]*gsv + gev*d0);
        atomicAdd(&g_dv[(rcv*3+1)*F + j], g_v[(snd*3+1)*F + j]*gsv + gev*d1);
        atomicAdd(&g_dv[(rcv*3+2)*F + j], g_v[(snd*3+2)*F + j]*gsv + gev*d2);
    }
}

__global__ void apply_k() {
    int idx = blockIdx.x * blockDim.x + threadIdx.x;
    if (idx >= NN*3*F) return;
    g_v[idx] += g_dv[idx];
    g_dv[idx] = 0.0f;
    if (idx < NN*F) { g_s[idx] += g_ds[idx]; g_ds[idx] = 0.0f; }
}

__global__ void prep_k() {
    int idx = blockIdx.x * blockDim.x + threadIdx.x;
    if (idx >= NN*F) return;
    int n = idx >> 7, j = idx & 127;
    float u0 = g_UVo[(size_t)(n*3+0)*256 + j];
    float u1 = g_UVo[(size_t)(n*3+1)*256 + j];
    float u2 = g_UVo[(size_t)(n*3+2)*256 + j];
    float w0 = g_UVo[(size_t)(n*3+0)*256 + 128 + j];
    float w1 = g_UVo[(size_t)(n*3+1)*256 + 128 + j];
    float w2 = g_UVo[(size_t)(n*3+2)*256 + 128 + j];
    g_dot[idx] = u0*w0 + u1*w1 + u2*w2;
    g_min[n*256 + j]       = g_s[idx];
    g_min[n*256 + 128 + j] = sqrtf(w0*w0 + w1*w1 + w2*w2);
}

__global__ void final_k(float* __restrict__ out, int l) {
    int idx = blockIdx.x * blockDim.x + threadIdx.x;
    if (idx >= NN*F) return;
    int n = idx >> 7, j = idx & 127;
    float ass = g_m[(size_t)n*384 + j];
    float asv = g_m[(size_t)n*384 + 128 + j];
    float avv = g_m[(size_t)n*384 + 256 + j];
    float sv = g_s[idx] + ass + asv * g_dot[idx];
    g_s[idx] = sv;
    size_t ob = ((size_t)(l*NN + n) * 4) * F + j;
    out[ob] = sv;
#pragma unroll
    for (int d = 0; d < 3; d++) {
        float uv = g_UVo[(size_t)(n*3+d)*256 + j];
        float vv = g_v[(n*3+d)*F + j] + avv * uv;
        g_v[(n*3+d)*F + j] = vv;
        out[ob + (size_t)(d+1)*F] = vv;
    }
}

// ---------------- host launcher ---------------------------------------------
static float* sym(const void* s) { void* p = nullptr; cudaGetSymbolAddress(&p, s); return (float*)p; }

extern "C" void kernel_launch(void* const* d_in, const int* in_sizes, int n_in,
                              void* d_out, int out_size) {
    (void)in_sizes; (void)n_in; (void)out_size;
    const float* atom_xyz = (const float*)d_in[0];
    const float* cell     = (const float*)d_in[1];
    const int*   nodes    = (const int*)  d_in[2];
    const int*   aedges   = (const int*)  d_in[3];
    const float* edisp    = (const float*)d_in[4];
    const float* Vflat    = (const float*)d_in[5];
    const float* Eflat    = (const float*)d_in[6];
    const float* emb      = (const float*)d_in[7];
    const float* potW     = (const float*)d_in[8];
    const float* potb     = (const float*)d_in[9];
    const float* iW1      = (const float*)d_in[10];
    const float* ib1      = (const float*)d_in[11];
    const float* iW2      = (const float*)d_in[12];
    const float* ib2      = (const float*)d_in[13];
    const float* vecw     = (const float*)d_in[14];
    const float* filtW    = (const float*)d_in[15];
    const float* filtb    = (const float*)d_in[16];
    const float* mW1      = (const float*)d_in[17];
    const float* mb1      = (const float*)d_in[18];
    const float* mW2      = (const float*)d_in[19];
    const float* mb2      = (const float*)d_in[20];
    const float* UW       = (const float*)d_in[21];
    const float* VW       = (const float*)d_in[22];
    const float* uW1      = (const float*)d_in[23];
    const float* ub1      = (const float*)d_in[24];
    const float* uW2      = (const float*)d_in[25];
    const float* ub2      = (const float*)d_in[26];
    float* out = (float*)d_out;

    float* ps   = sym(g_s);
    float* pv   = sym(g_v);
    float* pso  = sym(g_so);
    float* phid = sym(g_hid);
    float* pmin = sym(g_min);
    float* pm   = sym(g_m);
    float* pUVo = sym(g_UVo);
    float* pUVW = sym(g_UVW);
    float* pzb  = sym(g_zb);

    cudaFuncSetAttribute((const void*)gemm_mma<0>,
                         cudaFuncAttributeMaxDynamicSharedMemorySize, GSMEM);
    cudaFuncSetAttribute((const void*)gemm_mma<1>,
                         cudaFuncAttributeMaxDynamicSharedMemorySize, GSMEM);

    const int T = 256;
    const int NF_B   = (NN*F + T - 1) / T;
    const int N3F_B  = (NN*3*F + T - 1) / T;
    const int GEO_B  = (ETOT + T - 1) / T;
    const int MB  = NN / 128;     // 128 row-tiles
    const int MB3 = 3*NN / 128;   // 384 row-tiles

    reset_k<<<1, 1>>>();
    geom_k<<<GEO_B, T>>>(atom_xyz, cell, aedges, edisp);
    pack_uv_k<<<(NL*2*F*F + T - 1)/T, T>>>(UW, VW);

    init_h_k<<<NF_B, T>>>(nodes, Vflat, emb, potW, potb);
    gemm_mma<1><<<dim3(1, MB), T, GSMEM>>>(pmin, iW1, ib1, phid, F,   2*F);
    gemm_mma<0><<<dim3(1, MB), T, GSMEM>>>(phid, iW2, ib2, ps,   F,   F);
    init_v_k<<<N3F_B, T>>>(Eflat, vecw);

    for (int l = 0; l < NL; l++) {
        gemm_mma<1><<<dim3(1, MB), T, GSMEM>>>(ps,   mW1 + (size_t)l*F*F,   mb1 + l*F,   phid, F,   F);
        gemm_mma<0><<<dim3(3, MB), T, GSMEM>>>(phid, mW2 + (size_t)l*3*F*F, mb2 + l*3*F, pso,  3*F, F);
        edge_k<<<ETOT/EPB, 128>>>(filtW + (size_t)l*3*F*KF, filtb + (size_t)l*3*F);
        apply_k<<<N3F_B, T>>>();
        // [Uv | Vv] = v @ [UW|VW]^T  (3N x 256, packed weights)
        gemm_mma<0><<<dim3(2, MB3), T, GSMEM>>>(pv, pUVW + (size_t)l*256*F, pzb, pUVo, 256, F);
        prep_k<<<NF_B, T>>>();
        gemm_mma<1><<<dim3(1, MB), T, GSMEM>>>(pmin, uW1 + (size_t)l*F*2*F, ub1 + l*F,   phid, F,   2*F);
        gemm_mma<0><<<dim3(3, MB), T, GSMEM>>>(phid, uW2 + (size_t)l*3*F*F, ub2 + l*3*F, pm,   3*F, F);
        final_k<<<NF_B, T>>>(out, l);
    }
}